// round 1
// baseline (speedup 1.0000x reference)
#include <cuda_runtime.h>

// Einsum_56865366999610: the reference's HE-slot pipeline is algebraically
// exactly out = x @ y with x:[32,48], y:[48,32], fp32.
// W0/W1/W2 (one-hot layout matrices, ~1GB) are ignored — they only encode the
// slot permutation, which the direct matmul reproduces.
//
// One CTA, 1024 threads, inputs staged in shared memory, fully unrolled
// 48-term dot product per output element. Launch-latency bound by design.

#define I_DIM 32
#define J_DIM 48
#define K_DIM 32

__global__ __launch_bounds__(1024, 1)
void Einsum_56865366999610_kernel(const float* __restrict__ x,
                                  const float* __restrict__ y,
                                  float* __restrict__ out) {
    __shared__ float sx[I_DIM * J_DIM];   // 1536 floats
    __shared__ float sy[J_DIM * K_DIM];   // 1536 floats

    const int t = threadIdx.x;

    // Stage inputs: 1536 elements each, 1024 threads -> 1 full + 1 guarded pass.
    sx[t] = x[t];
    sy[t] = y[t];
    if (t < I_DIM * J_DIM - 1024) {       // t < 512
        sx[t + 1024] = x[t + 1024];
        sy[t + 1024] = y[t + 1024];
    }
    __syncthreads();

    // Thread t computes out[i,k]: i = t>>5 (warp-uniform), k = t&31.
    const int i = t >> 5;
    const int k = t & 31;

    const float* __restrict__ xr = &sx[i * J_DIM];  // warp-broadcast reads
    float acc = 0.0f;
#pragma unroll
    for (int j = 0; j < J_DIM; ++j) {
        acc = fmaf(xr[j], sy[j * K_DIM + k], acc);  // sy: conflict-free row
    }
    out[t] = acc;
}

extern "C" void kernel_launch(void* const* d_in, const int* in_sizes, int n_in,
                              void* d_out, int out_size) {
    // metadata order: x [32*48], y [48*32], W0, W1, W2 (unused).
    const float* x = (const float*)d_in[0];
    const float* y = (const float*)d_in[1];
    float* out = (float*)d_out;
    (void)in_sizes; (void)n_in; (void)out_size;

    Einsum_56865366999610_kernel<<<1, 1024>>>(x, y, out);
}

// round 2
// speedup vs baseline: 1.0052x; 1.0052x over previous
#include <cuda_runtime.h>

// Einsum_56865366999610 == out = x @ y, x:[32,48], y:[48,32], fp32.
// (The reference's HE-slot pipeline with W0/W1/W2 is algebraically this matmul;
//  the ~1GB one-hot matrices only encode a slot permutation.)
//
// R1 lesson: single-CTA smem version was LSU-issue-bound on one SM
// (3072 warp-LDS + 3072 warp-LDG on a single crossbar). This version uses
// 32 CTAs x 32 threads, direct global loads, no shared memory:
//   - y[j*32+k] : coalesced, 48 independent LDGs/thread (< MLP cap ~55)
//     -> DRAM latency paid once, overlapped.
//   - x[i*48+j] : warp-uniform broadcast loads, 2 lines per CTA.
//   - 4 split accumulators to shorten the FMA dependency chain.

#define J_DIM 48
#define K_DIM 32

__global__ __launch_bounds__(32, 1)
void Einsum_56865366999610_kernel(const float* __restrict__ x,
                                  const float* __restrict__ y,
                                  float* __restrict__ out) {
    const int i = blockIdx.x;     // output row
    const int k = threadIdx.x;    // output col (lane)

    const float* __restrict__ xr = x + i * J_DIM;
    const float* __restrict__ yc = y + k;

    // Issue all y loads up front (independent -> max MLP).
    float yv[J_DIM];
#pragma unroll
    for (int j = 0; j < J_DIM; ++j) {
        yv[j] = __ldg(yc + j * K_DIM);
    }

    // x row: warp-uniform broadcast loads.
    float xv[J_DIM];
#pragma unroll
    for (int j = 0; j < J_DIM; ++j) {
        xv[j] = __ldg(xr + j);
    }

    // 4-way split accumulation (chain length 12 instead of 48).
    float a0 = 0.f, a1 = 0.f, a2 = 0.f, a3 = 0.f;
#pragma unroll
    for (int j = 0; j < J_DIM; j += 4) {
        a0 = fmaf(xv[j + 0], yv[j + 0], a0);
        a1 = fmaf(xv[j + 1], yv[j + 1], a1);
        a2 = fmaf(xv[j + 2], yv[j + 2], a2);
        a3 = fmaf(xv[j + 3], yv[j + 3], a3);
    }
    out[i * K_DIM + k] = (a0 + a1) + (a2 + a3);
}

extern "C" void kernel_launch(void* const* d_in, const int* in_sizes, int n_in,
                              void* d_out, int out_size) {
    const float* x = (const float*)d_in[0];
    const float* y = (const float*)d_in[1];
    float* out = (float*)d_out;
    (void)in_sizes; (void)n_in; (void)out_size;

    Einsum_56865366999610_kernel<<<32, 32>>>(x, y, out);
}

// round 4
// speedup vs baseline: 1.2138x; 1.2075x over previous
#include <cuda_runtime.h>

// Einsum_56865366999610 == out = x @ y, x:[32,48], y:[48,32], fp32.
// (Reference's HE-slot pipeline with one-hot W0/W1/W2 is exactly this matmul.)
//
// R3 was an infra failure (container died twice); resubmitting the same
// experiment so the delta stays attributable.
//
// Theory: runtime = fixed ~5us launch/clock-ramp floor + small work margin.
// This round shaves the margin: warp-uniform x-row loads vectorized to
// 12 x LDG.128 (row base i*48 floats = 192B, always 16B-aligned), cutting
// per-thread LDG 96 -> 60 and shortening the prologue/register ramp.

#define J_DIM 48
#define K_DIM 32

__global__ __launch_bounds__(32, 1)
void Einsum_56865366999610_kernel(const float* __restrict__ x,
                                  const float* __restrict__ y,
                                  float* __restrict__ out) {
    const int i = blockIdx.x;     // output row
    const int k = threadIdx.x;    // output col (lane)

    const float4* __restrict__ xr4 =
        reinterpret_cast<const float4*>(x + i * J_DIM);  // 12 x float4, 16B-aligned
    const float* __restrict__ yc = y + k;

    // x row: 12 warp-uniform broadcast LDG.128 (independent -> full MLP).
    float4 xv[12];
#pragma unroll
    for (int q = 0; q < 12; ++q) {
        xv[q] = __ldg(xr4 + q);
    }

    // y column: 48 coalesced LDG.32 (lane k, stride 32 floats).
    float yv[J_DIM];
#pragma unroll
    for (int j = 0; j < J_DIM; ++j) {
        yv[j] = __ldg(yc + j * K_DIM);
    }

    // 4-way split accumulation; one float4 of x per step.
    float a0 = 0.f, a1 = 0.f, a2 = 0.f, a3 = 0.f;
#pragma unroll
    for (int q = 0; q < 12; ++q) {
        a0 = fmaf(xv[q].x, yv[4 * q + 0], a0);
        a1 = fmaf(xv[q].y, yv[4 * q + 1], a1);
        a2 = fmaf(xv[q].z, yv[4 * q + 2], a2);
        a3 = fmaf(xv[q].w, yv[4 * q + 3], a3);
    }
    out[i * K_DIM + k] = (a0 + a1) + (a2 + a3);
}

extern "C" void kernel_launch(void* const* d_in, const int* in_sizes, int n_in,
                              void* d_out, int out_size) {
    const float* x = (const float*)d_in[0];
    const float* y = (const float*)d_in[1];
    float* out = (float*)d_out;
    (void)in_sizes; (void)n_in; (void)out_size;

    Einsum_56865366999610_kernel<<<32, 32>>>(x, y, out);
}

// round 5
// speedup vs baseline: 1.2215x; 1.0063x over previous
#include <cuda_runtime.h>

// Einsum_56865366999610 == out = x @ y, x:[32,48], y:[48,32], fp32.
// (Reference's HE-slot pipeline with one-hot W0/W1/W2 is exactly this matmul.)
//
// R4 lesson: the 0.73us win from cutting 96->60 per-warp LDGs is explained by
// the per-warp outstanding-LDG cap (M_max ~55): R2 serialized a second L2
// round-trip for the over-cap loads. This round gets decisively under the cap:
// 2 warps per output row (j split 24/24), 30 outstanding LDGs per warp, half
// the FMA chain, one cheap smem exchange to combine the halves.

#define J_DIM 48
#define K_DIM 32
#define J_HALF 24

__global__ __launch_bounds__(64, 1)
void Einsum_56865366999610_kernel(const float* __restrict__ x,
                                  const float* __restrict__ y,
                                  float* __restrict__ out) {
    __shared__ float partial[K_DIM];

    const int t = threadIdx.x;
    const int w = t >> 5;         // warp: j-half
    const int k = t & 31;         // output col (lane)
    const int i = blockIdx.x;     // output row
    const int jb = w * J_HALF;    // 0 or 24

    // x row slice: 24 floats = 6 warp-uniform LDG.128 (base i*192+96w B, 16B-aligned).
    const float4* __restrict__ xr4 =
        reinterpret_cast<const float4*>(x + i * J_DIM + jb);
    const float* __restrict__ yc = y + jb * K_DIM + k;

    float4 xv[6];
#pragma unroll
    for (int q = 0; q < 6; ++q) {
        xv[q] = __ldg(xr4 + q);
    }

    // y column slice: 24 coalesced LDG.32.
    float yv[J_HALF];
#pragma unroll
    for (int j = 0; j < J_HALF; ++j) {
        yv[j] = __ldg(yc + j * K_DIM);
    }

    // 4-way split accumulation over 24 terms (chain length 6).
    float a0 = 0.f, a1 = 0.f, a2 = 0.f, a3 = 0.f;
#pragma unroll
    for (int q = 0; q < 6; ++q) {
        a0 = fmaf(xv[q].x, yv[4 * q + 0], a0);
        a1 = fmaf(xv[q].y, yv[4 * q + 1], a1);
        a2 = fmaf(xv[q].z, yv[4 * q + 2], a2);
        a3 = fmaf(xv[q].w, yv[4 * q + 3], a3);
    }
    const float sum = (a0 + a1) + (a2 + a3);

    // Combine the two j-halves: warp1 publishes, warp0 adds + stores.
    if (w == 1) partial[k] = sum;
    __syncthreads();
    if (w == 0) out[i * K_DIM + k] = sum + partial[k];
}

extern "C" void kernel_launch(void* const* d_in, const int* in_sizes, int n_in,
                              void* d_out, int out_size) {
    const float* x = (const float*)d_in[0];
    const float* y = (const float*)d_in[1];
    float* out = (float*)d_out;
    (void)in_sizes; (void)n_in; (void)out_size;

    Einsum_56865366999610_kernel<<<32, 64>>>(x, y, out);
}